// round 4
// baseline (speedup 1.0000x reference)
#include <cuda_runtime.h>
#include <cstdint>

#define SEQ 2048
#define HD 64
#define NBH 32
#define TOPK 32
#define WPB 4
#define LCAP 128
#define KPAD 68   // row stride in floats (16B-aligned, breaks 16-way bank conflicts)

__device__ __forceinline__ unsigned fkey(float f) {
    unsigned u = __float_as_uint(f);
    return (u & 0x80000000u) ? ~u : (u | 0x80000000u);
}

// ---------------------------------------------------------------------------
// Kernel 1: scores[bh,i,j] = (1/8) * sum_d q[bh,i,d] * k[bh,j,d]
// 64x64 output tile, 256 threads (16x16), 4x4 microtile per thread,
// row-major smem tiles with padded stride. Plain FFMA only.
// Smem: 2 * 64 * 68 * 4 B = 34816 B.
// ---------------------------------------------------------------------------
__global__ __launch_bounds__(256) void score_kernel(
    const float* __restrict__ q, const float* __restrict__ k,
    float* __restrict__ scores)
{
    __shared__ float Qs[64 * KPAD];   // [i][d], stride KPAD
    __shared__ float Ks[64 * KPAD];   // [j][d], stride KPAD

    const int t = threadIdx.x;
    const int bh = blockIdx.z;
    const float* qb = q + ((size_t)bh * SEQ + blockIdx.y * 64) * HD;
    const float* kb = k + ((size_t)bh * SEQ + blockIdx.x * 64) * HD;

    // Load tiles: 64 rows x 16 float4 each; 1024 float4 per tile, 4 per thread.
    // Consecutive threads -> consecutive d-chunks -> coalesced gmem reads and
    // conflict-free smem stores. Q scaled by 1/8 (exact power of two).
#pragma unroll
    for (int it = 0; it < 4; it++) {
        int idx = t + 256 * it;          // 0..1023
        int row = idx >> 4, d4 = idx & 15;
        float4 qa = *(const float4*)(qb + row * HD + d4 * 4);
        qa.x *= 0.125f; qa.y *= 0.125f; qa.z *= 0.125f; qa.w *= 0.125f;
        *(float4*)(Qs + row * KPAD + d4 * 4) = qa;
        float4 ka = *(const float4*)(kb + row * HD + d4 * 4);
        *(float4*)(Ks + row * KPAD + d4 * 4) = ka;
    }
    __syncthreads();

    const int ti = t >> 4, tj = t & 15;   // 16x16 grid, each does 4 i x 4 j
    float acc[4][4];
#pragma unroll
    for (int i = 0; i < 4; i++)
#pragma unroll
        for (int j = 0; j < 4; j++) acc[i][j] = 0.f;

#pragma unroll
    for (int dc = 0; dc < 16; dc++) {     // 4 d-values per chunk
        float4 a[4], b[4];
#pragma unroll
        for (int i = 0; i < 4; i++)
            a[i] = *(const float4*)(Qs + (ti * 4 + i) * KPAD + dc * 4);
#pragma unroll
        for (int j = 0; j < 4; j++)
            b[j] = *(const float4*)(Ks + (tj * 4 + j) * KPAD + dc * 4);
#pragma unroll
        for (int i = 0; i < 4; i++)
#pragma unroll
            for (int j = 0; j < 4; j++) {
                acc[i][j] = fmaf(a[i].x, b[j].x, acc[i][j]);
                acc[i][j] = fmaf(a[i].y, b[j].y, acc[i][j]);
                acc[i][j] = fmaf(a[i].z, b[j].z, acc[i][j]);
                acc[i][j] = fmaf(a[i].w, b[j].w, acc[i][j]);
            }
    }

    const size_t obase = ((size_t)bh * SEQ + blockIdx.y * 64 + ti * 4) * SEQ
                       + blockIdx.x * 64 + tj * 4;
#pragma unroll
    for (int i = 0; i < 4; i++) {
        float4 o = make_float4(acc[i][0], acc[i][1], acc[i][2], acc[i][3]);
        *(float4*)(scores + obase + (size_t)i * SEQ) = o;
    }
}

// ---------------------------------------------------------------------------
// Kernel 2: warp-per-row. Exact radix-select of the 32nd-largest score,
// masked softmax over kept entries, mask output, sparse context.
// Reads raw scores from the attn segment of d_out, overwrites in place.
// Fully deterministic: ballot-based compaction (ascending j), fixed-order sums.
// ---------------------------------------------------------------------------
__global__ __launch_bounds__(WPB * 32) void finalize_kernel(
    const float* __restrict__ v, const float* __restrict__ scores,
    float* __restrict__ ctx, float* __restrict__ attn, float* __restrict__ maskp)
{
    __shared__ float srow[WPB][SEQ];       // 32 KB
    __shared__ unsigned hist[WPB][256];    // 4 KB
    __shared__ int list[WPB][LCAP];        // 2 KB
    __shared__ float plist[WPB][LCAP];     // 2 KB

    const int w = threadIdx.x >> 5;
    const int lane = threadIdx.x & 31;
    const size_t R = (size_t)blockIdx.x * WPB + w;
    const int bh = (int)(R >> 11);

    // Stage the row in smem; row max on the way.
    const float4* g4 = (const float4*)(scores + R * SEQ);
    float4* s4 = (float4*)srow[w];
    float m = __int_as_float(0xff800000);
#pragma unroll
    for (int it = 0; it < 16; it++) {
        float4 val = g4[lane + 32 * it];
        s4[lane + 32 * it] = val;
        m = fmaxf(m, fmaxf(fmaxf(val.x, val.y), fmaxf(val.z, val.w)));
    }
#pragma unroll
    for (int off = 16; off >= 1; off >>= 1)
        m = fmaxf(m, __shfl_xor_sync(0xffffffffu, m, off));
    __syncwarp();

    // Exact 32nd-largest via 4x 8-bit radix rounds on order-preserving keys.
    unsigned prefix = 0, prefmask = 0, kk = TOPK;
    for (int shift = 24; shift >= 0; shift -= 8) {
#pragma unroll
        for (int e = 0; e < 8; e++) hist[w][lane + 32 * e] = 0;
        __syncwarp();
        for (int it = 0; it < 64; it++) {
            unsigned u = fkey(srow[w][lane + 32 * it]);
            if ((u & prefmask) == prefix)
                atomicAdd(&hist[w][(u >> shift) & 255u], 1u);
        }
        __syncwarp();
        unsigned p = 0;
#pragma unroll
        for (int b = 0; b < 8; b++) p += hist[w][lane * 8 + b];
        unsigned S = p;  // inclusive suffix sum over lanes >= lane
#pragma unroll
        for (int off = 1; off < 32; off <<= 1) {
            unsigned tv = __shfl_down_sync(0xffffffffu, S, off);
            if (lane + off < 32) S += tv;
        }
        unsigned sufExcl = S - p;
        bool mine = (S >= kk) && (sufExcl < kk);
        unsigned bal = __ballot_sync(0xffffffffu, mine);
        int src = __ffs(bal) - 1;
        unsigned chosen = 0, newk = 0;
        if (mine) {
            unsigned cum = sufExcl;
#pragma unroll
            for (int b = 7; b >= 0; b--) {
                unsigned h = hist[w][lane * 8 + b];
                if (cum + h >= kk) { chosen = lane * 8 + b; newk = kk - cum; break; }
                cum += h;
            }
        }
        chosen = __shfl_sync(0xffffffffu, chosen, src);
        newk = __shfl_sync(0xffffffffu, newk, src);
        prefix |= chosen << shift;
        prefmask |= 0xFFu << shift;
        kk = newk;
        __syncwarp();
    }
    const unsigned tkey = prefix;  // bit pattern of the 32nd-largest score

    // Streaming fills: attn = 0, mask = 1 (kept entries scattered below).
    float4* a4 = (float4*)(attn + R * SEQ);
    float4* m4 = maskp ? (float4*)(maskp + R * SEQ) : (float4*)0;
    const float4 zero4 = make_float4(0.f, 0.f, 0.f, 0.f);
    const float4 one4 = make_float4(1.f, 1.f, 1.f, 1.f);
#pragma unroll
    for (int it = 0; it < 16; it++) {
        a4[lane + 32 * it] = zero4;
        if (m4) m4[lane + 32 * it] = one4;
    }

    // Deterministic compaction of kept indices (ascending j).
    // keep <=> fkey(s) >= tkey <=> NOT(score < thresh).
    int base = 0;
    for (int it = 0; it < 64; it++) {
        int j = lane + 32 * it;
        bool keep = fkey(srow[w][j]) >= tkey;
        unsigned bal = __ballot_sync(0xffffffffu, keep);
        if (keep) {
            int pos = base + __popc(bal & ((1u << lane) - 1u));
            if (pos < LCAP) list[w][pos] = j;
        }
        base += __popc(bal);
    }
    __syncwarp();
    const int n = min(base, LCAP);

    // exp only on kept entries (~32); deterministic warp reduction.
    float lsum = 0.f;
    for (int e = lane; e < n; e += 32) {
        int j = list[w][e];
        float p = __expf(srow[w][j] - m);
        plist[w][e] = p;
        lsum += p;
    }
#pragma unroll
    for (int off = 16; off >= 1; off >>= 1)
        lsum += __shfl_xor_sync(0xffffffffu, lsum, off);
    const float inv = 1.0f / lsum;
    __syncwarp();

    // Scatter kept attn/mask; gather-accumulate context (fixed ascending order).
    const float* vb = v + (size_t)bh * SEQ * HD;
    float acc0 = 0.f, acc1 = 0.f;
    float* arow = attn + R * SEQ;
    float* mrow = maskp ? maskp + R * SEQ : (float*)0;
    for (int e = 0; e < n; e++) {
        int j = list[w][e];
        float wgt = plist[w][e] * inv;
        if (lane == 0) {
            arow[j] = wgt;
            if (mrow) mrow[j] = 0.f;
        }
        acc0 += wgt * vb[j * HD + lane];
        acc1 += wgt * vb[j * HD + lane + 32];
    }
    if (ctx) {
        ctx[R * HD + lane] = acc0;
        ctx[R * HD + lane + 32] = acc1;
    }
}

// ---------------------------------------------------------------------------
extern "C" void kernel_launch(void* const* d_in, const int* in_sizes, int n_in,
                              void* d_out, int out_size)
{
    if (n_in < 3 || !d_out) return;
    const float* q = (const float*)d_in[0];
    const float* k = (const float*)d_in[1];
    const float* v = (const float*)d_in[2];
    float* out = (float*)d_out;

    const size_t nctx = (size_t)NBH * SEQ * HD;        //   4,194,304
    const size_t nattn = (size_t)NBH * SEQ * SEQ;      // 134,217,728
    float* ctx = 0; float* attn = 0; float* maskp = 0;
    const size_t osz = (size_t)out_size;
    if (osz >= nctx + 2 * nattn) {            // (context, attn, mask) fp32
        ctx = out; attn = out + nctx; maskp = out + nctx + nattn;
    } else if (osz >= nctx + nattn) {         // (context, attn)
        ctx = out; attn = out + nctx;
    } else {                                  // attn only (stage in place)
        attn = out;
    }

    // Stage raw scores in the attn segment; kernel 2 overwrites it in place.
    score_kernel<<<dim3(SEQ / 64, SEQ / 64, NBH), 256>>>(q, k, attn);
    finalize_kernel<<<(NBH * SEQ) / WPB, WPB * 32>>>(v, attn, ctx, attn, maskp);
}

// round 5
// speedup vs baseline: 1.4872x; 1.4872x over previous
#include <cuda_runtime.h>
#include <cstdint>

#define SEQ 2048
#define HD 64
#define NBH 32
#define TOPK 32
#define WPB 4
#define LCAP 128
#define CAND_CAP 512

__device__ __forceinline__ unsigned long long dup2(float x) {
    unsigned long long r;
    asm("mov.b64 %0, {%1, %1};" : "=l"(r) : "f"(x));
    return r;
}
__device__ __forceinline__ void fma2(unsigned long long& c, unsigned long long a, unsigned long long b) {
    asm("fma.rn.f32x2 %0, %1, %2, %0;" : "+l"(c) : "l"(a), "l"(b));
}
__device__ __forceinline__ unsigned fkey(float f) {
    unsigned u = __float_as_uint(f);
    return (u & 0x80000000u) ? ~u : (u | 0x80000000u);
}
__device__ __forceinline__ float unfkey(unsigned k) {
    return (k & 0x80000000u) ? __uint_as_float(k & 0x7FFFFFFFu) : __uint_as_float(~k);
}

// ---------------------------------------------------------------------------
// Kernel 1: scores[bh,i,j] = (1/8) * sum_d q[bh,i,d] * k[bh,j,d]
// 128(i) x 64(j) tile, 128 threads, 8x8 microtile, packed f32x2 FMAs
// (3-reg FFMA is half-rate on sm_103a; f32x2 restores full rate).
// Also prefills mask = 1.0f over its tile (finalize scatters zeros for kept).
// ---------------------------------------------------------------------------
__global__ __launch_bounds__(128) void score_kernel(
    const float* __restrict__ q, const float* __restrict__ k,
    float* __restrict__ scores, float* __restrict__ maskp)
{
    __shared__ float QsT[HD * 128];   // [d][i], 32 KB
    __shared__ float KsT[HD * 64];    // [d][j], 16 KB  (total 48 KB static)

    const int t = threadIdx.x;
    const int bh = blockIdx.z;
    const float* qb = q + ((size_t)bh * SEQ + blockIdx.y * 128) * HD;
    const float* kb = k + ((size_t)bh * SEQ + blockIdx.x * 64) * HD;

    // Q tile, scaled by 1/8 (exact power of two -> bit-identical scores)
#pragma unroll
    for (int it = 0; it < 16; it++) {
        int idx = t + 128 * it;
        int d4 = idx >> 7, row = idx & 127;
        float4 val = *(const float4*)(qb + row * HD + d4 * 4);
        QsT[(d4 * 4 + 0) * 128 + row] = val.x * 0.125f;
        QsT[(d4 * 4 + 1) * 128 + row] = val.y * 0.125f;
        QsT[(d4 * 4 + 2) * 128 + row] = val.z * 0.125f;
        QsT[(d4 * 4 + 3) * 128 + row] = val.w * 0.125f;
    }
    // K tile
#pragma unroll
    for (int it = 0; it < 8; it++) {
        int idx = t + 128 * it;
        int d4 = idx >> 6, row = idx & 63;
        float4 val = *(const float4*)(kb + row * HD + d4 * 4);
        KsT[(d4 * 4 + 0) * 64 + row] = val.x;
        KsT[(d4 * 4 + 1) * 64 + row] = val.y;
        KsT[(d4 * 4 + 2) * 64 + row] = val.z;
        KsT[(d4 * 4 + 3) * 64 + row] = val.w;
    }
    __syncthreads();

    const int ti = t >> 3, tj = t & 7;   // 16 x 8 grid, 8x8 microtile
    unsigned long long acc[8][4];
#pragma unroll
    for (int i = 0; i < 8; i++)
#pragma unroll
        for (int p = 0; p < 4; p++) acc[i][p] = 0ull;

    const float4* Q4 = (const float4*)QsT;                       // row = 32 float4
    const unsigned long long* K2 = (const unsigned long long*)KsT; // row = 32 u64

#pragma unroll 8
    for (int d = 0; d < HD; d++) {
        float4 a0 = Q4[d * 32 + ti * 2];
        float4 a1 = Q4[d * 32 + ti * 2 + 1];
        unsigned long long b0 = K2[d * 32 + tj * 4 + 0];
        unsigned long long b1 = K2[d * 32 + tj * 4 + 1];
        unsigned long long b2 = K2[d * 32 + tj * 4 + 2];
        unsigned long long b3 = K2[d * 32 + tj * 4 + 3];
        float av[8] = {a0.x, a0.y, a0.z, a0.w, a1.x, a1.y, a1.z, a1.w};
#pragma unroll
        for (int i = 0; i < 8; i++) {
            unsigned long long ai = dup2(av[i]);
            fma2(acc[i][0], ai, b0);
            fma2(acc[i][1], ai, b1);
            fma2(acc[i][2], ai, b2);
            fma2(acc[i][3], ai, b3);
        }
    }

    const size_t obase = ((size_t)bh * SEQ + blockIdx.y * 128 + ti * 8) * SEQ
                       + blockIdx.x * 64 + tj * 8;
#pragma unroll
    for (int i = 0; i < 8; i++) {
        unsigned long long* o = (unsigned long long*)(scores + obase + (size_t)i * SEQ);
        o[0] = acc[i][0]; o[1] = acc[i][1]; o[2] = acc[i][2]; o[3] = acc[i][3];
    }
    if (maskp) {
        const float4 one4 = make_float4(1.f, 1.f, 1.f, 1.f);
#pragma unroll
        for (int i = 0; i < 8; i++) {
            float4* mo = (float4*)(maskp + obase + (size_t)i * SEQ);
            mo[0] = one4; mo[1] = one4;
        }
    }
}

// ---------------------------------------------------------------------------
// Kernel 2: warp-per-row. Keys staged once in smem; exact radix-select of the
// 32nd-largest (rounds 2-4 scan only the candidate bin), masked softmax over
// kept entries, sparse context. Mask already prefilled to 1 by kernel 1; only
// kept positions are set to 0 here. Fully deterministic (ballot compaction).
// ---------------------------------------------------------------------------
__global__ __launch_bounds__(WPB * 32) void finalize_kernel(
    const float* __restrict__ v, const float* __restrict__ scores,
    float* __restrict__ ctx, float* __restrict__ attn, float* __restrict__ maskp)
{
    __shared__ unsigned srow[WPB][SEQ];          // keys, 32 KB
    __shared__ unsigned hist[WPB][256];          // 4 KB
    __shared__ unsigned short cand[WPB][CAND_CAP]; // 4 KB
    __shared__ int list[WPB][LCAP];              // 2 KB
    __shared__ float plist[WPB][LCAP];           // 2 KB

    const int w = threadIdx.x >> 5;
    const int lane = threadIdx.x & 31;
    const size_t R = (size_t)blockIdx.x * WPB + w;
    const int bh = (int)(R >> 11);

    // Stage the row as order-preserving keys; track the row max.
    const float4* g4 = (const float4*)(scores + R * SEQ);
    uint4* s4 = (uint4*)srow[w];
    float m = __int_as_float(0xff800000);
#pragma unroll
    for (int it = 0; it < 16; it++) {
        float4 val = g4[lane + 32 * it];
        s4[lane + 32 * it] = make_uint4(fkey(val.x), fkey(val.y), fkey(val.z), fkey(val.w));
        m = fmaxf(m, fmaxf(fmaxf(val.x, val.y), fmaxf(val.z, val.w)));
    }
#pragma unroll
    for (int off = 16; off >= 1; off >>= 1)
        m = fmaxf(m, __shfl_xor_sync(0xffffffffu, m, off));
    __syncwarp();

    // ---- Round 1: histogram of the top byte over all 2048 keys ----
#pragma unroll
    for (int e = 0; e < 8; e++) hist[w][lane + 32 * e] = 0;
    __syncwarp();
    for (int it = 0; it < 64; it++)
        atomicAdd(&hist[w][srow[w][lane + 32 * it] >> 24], 1u);
    __syncwarp();

    unsigned prefix, prefmask, kk = TOPK;
    unsigned b1;
    {
        unsigned p = 0;
#pragma unroll
        for (int b = 0; b < 8; b++) p += hist[w][lane * 8 + b];
        unsigned S = p;
#pragma unroll
        for (int off = 1; off < 32; off <<= 1) {
            unsigned tv = __shfl_down_sync(0xffffffffu, S, off);
            if (lane + off < 32) S += tv;
        }
        unsigned sufExcl = S - p;
        bool mine = (S >= kk) && (sufExcl < kk);
        unsigned bal = __ballot_sync(0xffffffffu, mine);
        int src = __ffs(bal) - 1;
        unsigned chosen = 0, newk = 0;
        if (mine) {
            unsigned cum = sufExcl;
#pragma unroll
            for (int b = 7; b >= 0; b--) {
                unsigned h = hist[w][lane * 8 + b];
                if (cum + h >= kk) { chosen = lane * 8 + b; newk = kk - cum; break; }
                cum += h;
            }
        }
        b1 = __shfl_sync(0xffffffffu, chosen, src);
        kk = __shfl_sync(0xffffffffu, newk, src);
        prefix = b1 << 24;
        prefmask = 0xFF000000u;
    }
    __syncwarp();

    // ---- Compact candidate indices (top byte == b1), deterministic order ----
    int cbase = 0;
    for (int it = 0; it < 64; it++) {
        int j = lane + 32 * it;
        bool isc = (srow[w][j] >> 24) == b1;
        unsigned bal = __ballot_sync(0xffffffffu, isc);
        if (isc) {
            int pos = cbase + __popc(bal & ((1u << lane) - 1u));
            if (pos < CAND_CAP) cand[w][pos] = (unsigned short)j;
        }
        cbase += __popc(bal);
    }
    __syncwarp();
    const bool useCand = (cbase <= CAND_CAP);
    const int c = cbase < CAND_CAP ? cbase : CAND_CAP;

    // ---- Rounds 2-4 over candidates (or full row fallback) ----
#pragma unroll
    for (int shift = 16; shift >= 0; shift -= 8) {
#pragma unroll
        for (int e = 0; e < 8; e++) hist[w][lane + 32 * e] = 0;
        __syncwarp();
        if (useCand) {
            for (int e = lane; e < c; e += 32) {
                unsigned u = srow[w][cand[w][e]];
                if ((u & prefmask) == prefix)
                    atomicAdd(&hist[w][(u >> shift) & 255u], 1u);
            }
        } else {
            for (int it = 0; it < 64; it++) {
                unsigned u = srow[w][lane + 32 * it];
                if ((u & prefmask) == prefix)
                    atomicAdd(&hist[w][(u >> shift) & 255u], 1u);
            }
        }
        __syncwarp();
        unsigned p = 0;
#pragma unroll
        for (int b = 0; b < 8; b++) p += hist[w][lane * 8 + b];
        unsigned S = p;
#pragma unroll
        for (int off = 1; off < 32; off <<= 1) {
            unsigned tv = __shfl_down_sync(0xffffffffu, S, off);
            if (lane + off < 32) S += tv;
        }
        unsigned sufExcl = S - p;
        bool mine = (S >= kk) && (sufExcl < kk);
        unsigned bal = __ballot_sync(0xffffffffu, mine);
        int src = __ffs(bal) - 1;
        unsigned chosen = 0, newk = 0;
        if (mine) {
            unsigned cum = sufExcl;
#pragma unroll
            for (int b = 7; b >= 0; b--) {
                unsigned h = hist[w][lane * 8 + b];
                if (cum + h >= kk) { chosen = lane * 8 + b; newk = kk - cum; break; }
                cum += h;
            }
        }
        chosen = __shfl_sync(0xffffffffu, chosen, src);
        kk = __shfl_sync(0xffffffffu, newk, src);
        prefix |= chosen << shift;
        prefmask |= 0xFFu << shift;
        __syncwarp();
    }
    const unsigned tkey = prefix;  // exact key bits of the 32nd-largest score

    // ---- attn = 0 streaming fill (kept entries scattered below) ----
    float4* a4 = (float4*)(attn + R * SEQ);
    const float4 zero4 = make_float4(0.f, 0.f, 0.f, 0.f);
#pragma unroll
    for (int it = 0; it < 16; it++) a4[lane + 32 * it] = zero4;

    // ---- Deterministic compaction of kept indices (key >= tkey) ----
    int base = 0;
    for (int it = 0; it < 64; it++) {
        int j = lane + 32 * it;
        bool keep = srow[w][j] >= tkey;
        unsigned bal = __ballot_sync(0xffffffffu, keep);
        if (keep) {
            int pos = base + __popc(bal & ((1u << lane) - 1u));
            if (pos < LCAP) list[w][pos] = j;
        }
        base += __popc(bal);
    }
    __syncwarp();
    const int n = base < LCAP ? base : LCAP;

    // exp only on kept entries; deterministic warp reduction of Z.
    float lsum = 0.f;
    for (int e = lane; e < n; e += 32) {
        float s = unfkey(srow[w][list[w][e]]);
        float p = __expf(s - m);
        plist[w][e] = p;
        lsum += p;
    }
#pragma unroll
    for (int off = 16; off >= 1; off >>= 1)
        lsum += __shfl_xor_sync(0xffffffffu, lsum, off);
    const float inv = 1.0f / lsum;
    __syncwarp();

    // Scatter kept attn / mask=0; gather-accumulate context (fixed order).
    const float* vb = v + (size_t)bh * SEQ * HD;
    float acc0 = 0.f, acc1 = 0.f;
    float* arow = attn + R * SEQ;
    float* mrow = maskp ? maskp + R * SEQ : (float*)0;
    for (int e = 0; e < n; e++) {
        int j = list[w][e];
        float wgt = plist[w][e] * inv;
        if (lane == 0) {
            arow[j] = wgt;
            if (mrow) mrow[j] = 0.f;
        }
        acc0 += wgt * vb[j * HD + lane];
        acc1 += wgt * vb[j * HD + lane + 32];
    }
    if (ctx) {
        ctx[R * HD + lane] = acc0;
        ctx[R * HD + lane + 32] = acc1;
    }
}

// ---------------------------------------------------------------------------
extern "C" void kernel_launch(void* const* d_in, const int* in_sizes, int n_in,
                              void* d_out, int out_size)
{
    if (n_in < 3 || !d_out) return;
    const float* q = (const float*)d_in[0];
    const float* k = (const float*)d_in[1];
    const float* v = (const float*)d_in[2];
    float* out = (float*)d_out;

    const size_t nctx = (size_t)NBH * SEQ * HD;        //   4,194,304
    const size_t nattn = (size_t)NBH * SEQ * SEQ;      // 134,217,728
    float* ctx = 0; float* attn = 0; float* maskp = 0;
    const size_t osz = (size_t)out_size;
    if (osz >= nctx + 2 * nattn) {            // (context, attn, mask) fp32
        ctx = out; attn = out + nctx; maskp = out + nctx + nattn;
    } else if (osz >= nctx + nattn) {         // (context, attn)
        ctx = out; attn = out + nctx;
    } else {                                  // attn only (stage in place)
        attn = out;
    }

    // Kernel 1 stages raw scores in the attn segment and prefills mask = 1.
    score_kernel<<<dim3(SEQ / 64, SEQ / 128, NBH), 128>>>(q, k, attn, maskp);
    finalize_kernel<<<(NBH * SEQ) / WPB, WPB * 32>>>(v, attn, ctx, attn, maskp);
}